// round 15
// baseline (speedup 1.0000x reference)
#include <cuda_runtime.h>
#include <cuda_bf16.h>
#include <cstdint>

// ---------------------------------------------------------------------------
// RelativeSelfAttention: B=4, L=1024, E=1024, H=16, D=64, K=64 (129 PE rows)
// R15: mma_gemm -> 256x128 tile, 512 threads, 3-stage single-sync pipeline
//      (SPAD 40 = proven conflict-free stride). g_Q fp32 removed.
// ---------------------------------------------------------------------------

#define NBH   64
#define BSTR  132

__device__ float g_bias[NBH * 1024 * BSTR];

__device__ __nv_bfloat16 g_Ahi[4096 * 1024], g_Alo[4096 * 1024];
__device__ __nv_bfloat16 g_Whi[3072 * 1024], g_Wlo[3072 * 1024];
__device__ __nv_bfloat16 g_OWhi[1024 * 1024], g_OWlo[1024 * 1024];
__device__ __nv_bfloat16 g_Xhi[4096 * 1024], g_Xlo[4096 * 1024];
__device__ __nv_bfloat16 g_Qhi[NBH * 65536], g_Qlo[NBH * 65536];
__device__ __nv_bfloat16 g_Khi[NBH * 65536], g_Klo[NBH * 65536];
__device__ __nv_bfloat16 g_Vhi[NBH * 65536], g_Vlo[NBH * 65536];

// ------------------------------- PTX helpers -------------------------------
__device__ __forceinline__ uint32_t s2u(const void* p) {
    return (uint32_t)__cvta_generic_to_shared(p);
}
__device__ __forceinline__ void ldsm_x4(uint32_t* r, uint32_t addr) {
    asm volatile("ldmatrix.sync.aligned.m8n8.x4.shared.b16 {%0,%1,%2,%3}, [%4];"
        : "=r"(r[0]), "=r"(r[1]), "=r"(r[2]), "=r"(r[3]) : "r"(addr));
}
__device__ __forceinline__ void ldsm_x4_t(uint32_t* r, uint32_t addr) {
    asm volatile("ldmatrix.sync.aligned.m8n8.x4.trans.shared.b16 {%0,%1,%2,%3}, [%4];"
        : "=r"(r[0]), "=r"(r[1]), "=r"(r[2]), "=r"(r[3]) : "r"(addr));
}
__device__ __forceinline__ void mma16816(float* c, const uint32_t* a,
                                         const uint32_t* b) {
    asm volatile(
        "mma.sync.aligned.m16n8k16.row.col.f32.bf16.bf16.f32 "
        "{%0,%1,%2,%3}, {%4,%5,%6,%7}, {%8,%9}, {%0,%1,%2,%3};"
        : "+f"(c[0]), "+f"(c[1]), "+f"(c[2]), "+f"(c[3])
        : "r"(a[0]), "r"(a[1]), "r"(a[2]), "r"(a[3]), "r"(b[0]), "r"(b[1]));
}
__device__ __forceinline__ void cpa16(uint32_t dst, const void* src) {
    asm volatile("cp.async.cg.shared.global [%0], [%1], 16;"
                 :: "r"(dst), "l"(src) : "memory");
}
__device__ __forceinline__ void cpa_commit() {
    asm volatile("cp.async.commit_group;" ::: "memory");
}
template <int N>
__device__ __forceinline__ void cpa_wait() {
    asm volatile("cp.async.wait_group %0;" :: "n"(N) : "memory");
}
__device__ __forceinline__ void pack_hl(float v0, float v1,
                                        uint32_t& hi, uint32_t& lo) {
    __nv_bfloat16 h0 = __float2bfloat16(v0), h1 = __float2bfloat16(v1);
    float l0 = v0 - __bfloat162float(h0), l1 = v1 - __bfloat162float(h1);
    __nv_bfloat162 H; H.x = h0; H.y = h1;
    __nv_bfloat162 L; L.x = __float2bfloat16(l0); L.y = __float2bfloat16(l1);
    hi = *(uint32_t*)&H; lo = *(uint32_t*)&L;
}
__device__ __forceinline__ void split2(__nv_bfloat16* hp, __nv_bfloat16* lp,
                                       size_t idx, float v0, float v1) {
    uint32_t hi, lo;
    pack_hl(v0, v1, hi, lo);
    *(uint32_t*)&hp[idx] = hi;
    *(uint32_t*)&lp[idx] = lo;
}

// ---------------------------------------------------------------------------
// Merged fp32 -> bf16 hi/lo split for q, W3, out_w (single launch).
// ---------------------------------------------------------------------------
__global__ __launch_bounds__(256) void split_all(
    const float* __restrict__ q, const float* __restrict__ w3,
    const float* __restrict__ ow)
{
    int i = blockIdx.x * 256 + threadIdx.x;
    const float* src;
    __nv_bfloat16 *hp, *lp;
    int off;
    if (i < 1048576)      { src = q;  hp = g_Ahi;  lp = g_Alo;  off = i; }
    else if (i < 1835008) { src = w3; hp = g_Whi;  lp = g_Wlo;  off = i - 1048576; }
    else                  { src = ow; hp = g_OWhi; lp = g_OWlo; off = i - 1835008; }
    float4 v = ((const float4*)src)[off];
    __nv_bfloat16 h[4], l[4];
    float f[4] = {v.x, v.y, v.z, v.w};
    #pragma unroll
    for (int k = 0; k < 4; ++k) {
        h[k] = __float2bfloat16(f[k]);
        l[k] = __float2bfloat16(f[k] - __bfloat162float(h[k]));
    }
    *(uint2*)&hp[(size_t)off * 4] = *(uint2*)h;
    *(uint2*)&lp[(size_t)off * 4] = *(uint2*)l;
}

// ---------------------------------------------------------------------------
// Split-bf16 mma.sync GEMM: 256x128 tile, 512 threads (16 warps, 4m x 4n),
// 3-stage cp.async pipeline, ONE __syncthreads per K-chunk (32 wide).
// Stage: Ah/Al 256x80B + Bh/Bl 128x80B = 61440 B; 3 stages = 180 KB, 1 CTA/SM.
// MODE 0: A=q-split,B=W3-split -> Q/K/V bf16-split
// MODE 1: A=X-split,B=out_w-split -> outp
// ---------------------------------------------------------------------------
#define SPAD 40
#define A_ARR_B (256 * 80)          // 20480
#define B_ARR_B (128 * 80)          // 10240
#define STG_B (2 * A_ARR_B + 2 * B_ARR_B)   // 61440
#define GEMM_SMEM (3 * STG_B)               // 184320

template <int MODE>
__global__ __launch_bounds__(512, 1) void mma_gemm(
    const float* __restrict__ bias, float* __restrict__ outp)
{
    extern __shared__ __align__(16) char gsm[];
    const uint32_t u0 = s2u(gsm);

    const __nv_bfloat16* Ah = (MODE == 0) ? g_Ahi : g_Xhi;
    const __nv_bfloat16* Al = (MODE == 0) ? g_Alo : g_Xlo;
    const __nv_bfloat16* Bh = (MODE == 0) ? g_Whi : g_OWhi;
    const __nv_bfloat16* Bl = (MODE == 0) ? g_Wlo : g_OWlo;

    const int m0 = blockIdx.y << 8;
    const int n0 = blockIdx.x << 7;
    const int tid = threadIdx.x;
    const int wid = tid >> 5, lane = tid & 31;
    const int wm = wid >> 2, wn = wid & 3;
    const int grp = lane >> 2, tig = lane & 3;

    // loaders: A 1024 uint4/array (2 per thread: rows r, r+128); B 512 (1 each)
    const int ar0 = tid >> 2, ac = tid & 3;        // A row 0..127 (+128), col 0..3
    const uint32_t ad0 = (uint32_t)(ar0 * 80) + (uint32_t)ac * 16;
    const uint32_t ad1 = ad0 + 128 * 80;
    const int br = tid >> 2, bc = tid & 3;         // B row 0..127, col 0..3

    // fragment smem byte offsets
    const uint32_t aBase = (uint32_t)((wm * 64 + (lane & 15)) * 80) +
                           (uint32_t)(lane >> 4) * 16;
    const uint32_t bBase = (uint32_t)((wn * 32 + (lane & 7)) * 80) +
                           (uint32_t)((lane >> 3) & 1) * 16;

    float acc[4][4][4] = {};

    auto issue = [&](int stage, int kc) {
        const uint32_t s = u0 + (uint32_t)stage * STG_B;
        const size_t ga0 = (size_t)(m0 + ar0) * 128 + kc * 4 + ac;
        const size_t ga1 = (size_t)(m0 + ar0 + 128) * 128 + kc * 4 + ac;
        const size_t gb  = (size_t)(n0 + br) * 128 + kc * 4 + bc;
        cpa16(s + ad0,              (const uint4*)Ah + ga0);
        cpa16(s + ad1,              (const uint4*)Ah + ga1);
        cpa16(s + A_ARR_B + ad0,    (const uint4*)Al + ga0);
        cpa16(s + A_ARR_B + ad1,    (const uint4*)Al + ga1);
        const uint32_t bd = (uint32_t)(br * 80) + (uint32_t)bc * 16;
        cpa16(s + 2 * A_ARR_B + bd,           (const uint4*)Bh + gb);
        cpa16(s + 2 * A_ARR_B + B_ARR_B + bd, (const uint4*)Bl + gb);
        cpa_commit();
    };

    issue(0, 0);
    issue(1, 1);

    for (int kc = 0; kc < 32; ++kc) {
        cpa_wait<1>();          // data for chunk kc resident
        __syncthreads();        // everyone done reading stage (kc-1)%3
        if (kc + 2 < 32) issue((kc + 2) % 3, kc + 2);
        else cpa_commit();      // empty group keeps wait<1> sound at tail

        const uint32_t sb = u0 + (uint32_t)(kc % 3) * STG_B;
        const uint32_t uAh = sb;
        const uint32_t uAl = sb + A_ARR_B;
        const uint32_t uBh = sb + 2 * A_ARR_B;
        const uint32_t uBl = uBh + B_ARR_B;

        #pragma unroll
        for (int ks = 0; ks < 2; ++ks) {
            const uint32_t kb = (uint32_t)(ks * 32);   // 16 bf16 = 32 B
            uint32_t fbh[4][2], fbl[4][2];
            #pragma unroll
            for (int ni = 0; ni < 4; ++ni) {
                uint32_t off = bBase + kb + (uint32_t)(ni * 8 * 80);
                asm volatile("ldmatrix.sync.aligned.m8n8.x2.shared.b16 {%0,%1}, [%2];"
                    : "=r"(fbh[ni][0]), "=r"(fbh[ni][1]) : "r"(uBh + off));
                asm volatile("ldmatrix.sync.aligned.m8n8.x2.shared.b16 {%0,%1}, [%2];"
                    : "=r"(fbl[ni][0]), "=r"(fbl[ni][1]) : "r"(uBl + off));
            }
            #pragma unroll
            for (int mi = 0; mi < 4; ++mi) {
                uint32_t fah[4], fal[4];
                uint32_t off = aBase + kb + (uint32_t)(mi * 16 * 80);
                ldsm_x4(fah, uAh + off);
                ldsm_x4(fal, uAl + off);
                #pragma unroll
                for (int ni = 0; ni < 4; ++ni) {
                    mma16816(acc[mi][ni], fah, fbh[ni]);
                    mma16816(acc[mi][ni], fah, fbl[ni]);
                    mma16816(acc[mi][ni], fal, fbh[ni]);
                }
            }
        }
    }

    #pragma unroll
    for (int mi = 0; mi < 4; ++mi) {
        #pragma unroll
        for (int ni = 0; ni < 4; ++ni) {
            const int col = n0 + wn * 32 + ni * 8 + tig * 2;
            const float bv0 = bias[col], bv1 = bias[col + 1];
            #pragma unroll
            for (int rh = 0; rh < 2; ++rh) {
                const int row = m0 + wm * 64 + mi * 16 + grp + rh * 8;
                float v0 = acc[mi][ni][rh * 2 + 0] + bv0;
                float v1 = acc[mi][ni][rh * 2 + 1] + bv1;
                if (MODE == 0) {
                    const int part = col >> 10;
                    const int h = (col & 1023) >> 6;
                    const int d = col & 63;
                    const int b = row >> 10, l = row & 1023;
                    size_t idx = ((size_t)((b << 4) + h) * 1024 + l) * 64 + d;
                    if (part == 0) {
                        split2(g_Qhi, g_Qlo, idx, v0 * 0.125f, v1 * 0.125f);
                    } else if (part == 1) {
                        split2(g_Khi, g_Klo, idx, v0, v1);
                    } else {
                        split2(g_Vhi, g_Vlo, idx, v0, v1);
                    }
                } else {
                    float2 o = {v0, v1};
                    *(float2*)&outp[row * 1024 + col] = o;
                }
            }
        }
    }
}

// ---------------------------------------------------------------------------
// Stage 2: bias_r[row, r] = q_scaled[row,:] . rel_pe[r,:]
// q reconstructed from bf16 hi+lo (error ~2^-19). Conflict-free pes_t.
// ---------------------------------------------------------------------------
__global__ __launch_bounds__(256) void bias_gemm(const float* __restrict__ pe)
{
    __shared__ float pes_t[64 * 132];
    __shared__ float qs[64 * 64];
    const int tid = threadIdx.x;
    const int row0 = blockIdx.x << 6;
    for (int i = tid; i < 129 * 64; i += 256) {
        int r = i >> 6, d = i & 63;
        pes_t[d * 132 + r] = pe[i];
    }
    for (int i = tid; i < 64 * 64; i += 256) {
        size_t g = (size_t)row0 * 64 + i;
        qs[i] = __bfloat162float(g_Qhi[g]) + __bfloat162float(g_Qlo[g]);
    }
    __syncthreads();
    for (int idx = tid; idx < 64 * 129; idx += 256) {
        int r = idx / 129, c = idx - r * 129;
        const float* qrow = &qs[r << 6];
        float s = 0.f;
        #pragma unroll
        for (int d = 0; d < 64; ++d)
            s = fmaf(qrow[d], pes_t[d * 132 + c], s);
        g_bias[(size_t)(row0 + r) * BSTR + c] = s;
    }
}

// ---------------------------------------------------------------------------
// Stage 3: flash attention (unchanged from R12/R14)
// ---------------------------------------------------------------------------
#define AT_SPAD 72
#define AT_ARR_B (64 * AT_SPAD * 2)
#define AT_STG_B (4 * AT_ARR_B)
#define AT_Q_B   (128 * AT_SPAD * 2)
#define ATTN_SMEM (2 * AT_STG_B + 2 * AT_Q_B)
#define NJT 16

__global__ __launch_bounds__(256, 2) void attn_mma()
{
    extern __shared__ __align__(16) char smem_raw[];
    const uint32_t u0 = s2u(smem_raw);
    const uint32_t uQh = u0 + 2 * AT_STG_B;
    const uint32_t uQl = uQh + AT_Q_B;

    const int bh = blockIdx.y;
    const int i0 = blockIdx.x << 7;
    const int tid = threadIdx.x;
    const int w = tid >> 5, lane = tid & 31;
    const int grp = lane >> 2, tig = lane & 3;

    const uint4* gKh = (const uint4*)(g_Khi + (size_t)bh * 65536);
    const uint4* gKl = (const uint4*)(g_Klo + (size_t)bh * 65536);
    const uint4* gVh = (const uint4*)(g_Vhi + (size_t)bh * 65536);
    const uint4* gVl = (const uint4*)(g_Vlo + (size_t)bh * 65536);

    const int cr = tid >> 2;
    const int cc = (tid & 3) * 2;
    const uint32_t cdst = (uint32_t)(cr * AT_SPAD * 2) + (uint32_t)cc * 16;
    auto issue_kv = [&](int jt) {
        const uint32_t s = u0 + (uint32_t)(jt & 1) * AT_STG_B;
        const uint4* kh = gKh + jt * 512 + cr * 8 + cc;
        const uint4* kl = gKl + jt * 512 + cr * 8 + cc;
        const uint4* vh = gVh + jt * 512 + cr * 8 + cc;
        const uint4* vl = gVl + jt * 512 + cr * 8 + cc;
        cpa16(s + cdst, kh);                    cpa16(s + cdst + 16, kh + 1);
        cpa16(s + AT_ARR_B + cdst, kl);         cpa16(s + AT_ARR_B + cdst + 16, kl + 1);
        cpa16(s + 2 * AT_ARR_B + cdst, vh);     cpa16(s + 2 * AT_ARR_B + cdst + 16, vh + 1);
        cpa16(s + 3 * AT_ARR_B + cdst, vl);     cpa16(s + 3 * AT_ARR_B + cdst + 16, vl + 1);
        cpa_commit();
    };

    issue_kv(0);

    {
        const size_t qbase = (size_t)bh * 65536 + (size_t)i0 * 64;
        const uint4* srcH = (const uint4*)(g_Qhi + qbase);
        const uint4* srcL = (const uint4*)(g_Qlo + qbase);
        __nv_bfloat16* tQh = (__nv_bfloat16*)(smem_raw + 2 * AT_STG_B);
        __nv_bfloat16* tQl = tQh + 128 * AT_SPAD;
        #pragma unroll
        for (int k = 0; k < 4; ++k) {
            int u = tid + k * 256;
            int r = u >> 3, c = (u & 7) * 8;
            *(uint4*)&tQh[r * AT_SPAD + c] = srcH[u];
            *(uint4*)&tQl[r * AT_SPAD + c] = srcL[u];
        }
    }

    const int r0g = i0 + w * 16 + grp;
    const int r1g = r0g + 8;
    const float* browG0 = g_bias + (size_t)(bh * 1024 + r0g) * BSTR + 64;
    const float* browG1 = g_bias + (size_t)(bh * 1024 + r1g) * BSTR + 64;
    const float clo0 = __ldg(browG0 - 64), chi0 = __ldg(browG0 + 64);
    const float clo1 = __ldg(browG1 - 64), chi1 = __ldg(browG1 + 64);

    float mr[2] = {-1e30f, -1e30f};
    float lr[2] = {0.f, 0.f};
    float o[8][4] = {};

    const uint32_t qro = (uint32_t)((w * 16 + (lane & 15)) * AT_SPAD +
                                    (lane >> 4) * 8) * 2;

    for (int jt = 0; jt < NJT; ++jt) {
        if (jt + 1 < NJT) issue_kv(jt + 1);
        if (jt + 1 < NJT) cpa_wait<1>(); else cpa_wait<0>();
        __syncthreads();

        const uint32_t uKh = u0 + (uint32_t)(jt & 1) * AT_STG_B;
        const uint32_t uKl = uKh + AT_ARR_B;
        const uint32_t uVh = uKl + AT_ARR_B;
        const uint32_t uVl = uVh + AT_ARR_B;
        const int j0 = jt << 6;

        float s[8][4];
        #pragma unroll
        for (int jb = 0; jb < 8; ++jb)
            #pragma unroll
            for (int e = 0; e < 4; ++e) s[jb][e] = 0.f;

        #pragma unroll
        for (int ks = 0; ks < 4; ++ks) {
            uint32_t qh[4], ql[4];
            ldsm_x4(qh, uQh + qro + ks * 32);
            ldsm_x4(ql, uQl + qro + ks * 32);
            #pragma unroll
            for (int jp = 0; jp < 4; ++jp) {
                uint32_t kfh[4], kfl[4];
                uint32_t off = (uint32_t)((jp * 16 + (lane & 7) +
                                           ((lane >> 4) << 3)) * AT_SPAD +
                                          ks * 16 + ((lane >> 3) & 1) * 8) * 2;
                ldsm_x4(kfh, uKh + off);
                ldsm_x4(kfl, uKl + off);
                mma16816(s[2 * jp],     qh, kfh);
                mma16816(s[2 * jp],     qh, kfl);
                mma16816(s[2 * jp],     ql, kfh);
                mma16816(s[2 * jp + 1], qh, kfh + 2);
                mma16816(s[2 * jp + 1], qh, kfl + 2);
                mma16816(s[2 * jp + 1], ql, kfh + 2);
            }
        }

        if (j0 + 63 - r0g <= -64) {
            #pragma unroll
            for (int jb = 0; jb < 8; ++jb) { s[jb][0] += clo0; s[jb][1] += clo0; }
        } else if (j0 - r0g >= 64) {
            #pragma unroll
            for (int jb = 0; jb < 8; ++jb) { s[jb][0] += chi0; s[jb][1] += chi0; }
        } else {
            const int dbase0 = j0 + tig * 2 - r0g;
            #pragma unroll
            for (int jb = 0; jb < 8; ++jb) {
                int dA = min(max(dbase0 + jb * 8,     -64), 64);
                int dB = min(max(dbase0 + jb * 8 + 1, -64), 64);
                s[jb][0] += __ldg(browG0 + dA);
                s[jb][1] += __ldg(browG0 + dB);
            }
        }
        if (j0 + 63 - r1g <= -64) {
            #pragma unroll
            for (int jb = 0; jb < 8; ++jb) { s[jb][2] += clo1; s[jb][3] += clo1; }
        } else if (j0 - r1g >= 64) {
            #pragma unroll
            for (int jb = 0; jb < 8; ++jb) { s[jb][2] += chi1; s[jb][3] += chi1; }
        } else {
            const int dbase1 = j0 + tig * 2 - r1g;
            #pragma unroll
            for (int jb = 0; jb < 8; ++jb) {
                int dC = min(max(dbase1 + jb * 8,     -64), 64);
                int dD = min(max(dbase1 + jb * 8 + 1, -64), 64);
                s[jb][2] += __ldg(browG1 + dC);
                s[jb][3] += __ldg(browG1 + dD);
            }
        }

        float mx0 = -1e30f, mx1 = -1e30f;
        #pragma unroll
        for (int jb = 0; jb < 8; ++jb) {
            mx0 = fmaxf(mx0, fmaxf(s[jb][0], s[jb][1]));
            mx1 = fmaxf(mx1, fmaxf(s[jb][2], s[jb][3]));
        }
        mx0 = fmaxf(mx0, __shfl_xor_sync(0xffffffffu, mx0, 1));
        mx0 = fmaxf(mx0, __shfl_xor_sync(0xffffffffu, mx0, 2));
        mx1 = fmaxf(mx1, __shfl_xor_sync(0xffffffffu, mx1, 1));
        mx1 = fmaxf(mx1, __shfl_xor_sync(0xffffffffu, mx1, 2));
        float nm0 = fmaxf(mr[0], mx0), nm1 = fmaxf(mr[1], mx1);
        float sc0 = __expf(mr[0] - nm0), sc1 = __expf(mr[1] - nm1);
        float ps0 = 0.f, ps1 = 0.f;
        #pragma unroll
        for (int jb = 0; jb < 8; ++jb) {
            s[jb][0] = __expf(s[jb][0] - nm0);
            s[jb][1] = __expf(s[jb][1] - nm0);
            s[jb][2] = __expf(s[jb][2] - nm1);
            s[jb][3] = __expf(s[jb][3] - nm1);
            ps0 += s[jb][0] + s[jb][1];
            ps1 += s[jb][2] + s[jb][3];
        }
        ps0 += __shfl_xor_sync(0xffffffffu, ps0, 1);
        ps0 += __shfl_xor_sync(0xffffffffu, ps0, 2);
        ps1 += __shfl_xor_sync(0xffffffffu, ps1, 1);
        ps1 += __shfl_xor_sync(0xffffffffu, ps1, 2);
        lr[0] = lr[0] * sc0 + ps0; mr[0] = nm0;
        lr[1] = lr[1] * sc1 + ps1; mr[1] = nm1;
        #pragma unroll
        for (int nd = 0; nd < 8; ++nd) {
            o[nd][0] *= sc0; o[nd][1] *= sc0;
            o[nd][2] *= sc1; o[nd][3] *= sc1;
        }

        #pragma unroll
        for (int kk = 0; kk < 4; ++kk) {
            uint32_t ah[4], al[4];
            pack_hl(s[2 * kk][0],     s[2 * kk][1],     ah[0], al[0]);
            pack_hl(s[2 * kk][2],     s[2 * kk][3],     ah[1], al[1]);
            pack_hl(s[2 * kk + 1][0], s[2 * kk + 1][1], ah[2], al[2]);
            pack_hl(s[2 * kk + 1][2], s[2 * kk + 1][3], ah[3], al[3]);
            #pragma unroll
            for (int np = 0; np < 4; ++np) {
                uint32_t vfh[4], vfl[4];
                uint32_t off = (uint32_t)((kk * 16 + (lane & 7) +
                                           ((lane >> 3) & 1) * 8) * AT_SPAD +
                                          np * 16 + (lane >> 4) * 8) * 2;
                ldsm_x4_t(vfh, uVh + off);
                ldsm_x4_t(vfl, uVl + off);
                mma16816(o[2 * np],     ah, vfh);
                mma16816(o[2 * np],     ah, vfl);
                mma16816(o[2 * np],     al, vfh);
                mma16816(o[2 * np + 1], ah, vfh + 2);
                mma16816(o[2 * np + 1], ah, vfl + 2);
                mma16816(o[2 * np + 1], al, vfh + 2);
            }
        }
        __syncthreads();
    }

    const float inv0 = 1.0f / lr[0], inv1 = 1.0f / lr[1];
    const int b = bh >> 4, h = bh & 15;
    const size_t row0 = (size_t)(b * 1024 + i0 + w * 16 + grp);
    const size_t row1 = row0 + 8;
    #pragma unroll
    for (int nd = 0; nd < 8; ++nd) {
        const int col = h * 64 + nd * 8 + tig * 2;
        uint32_t hi, lo;
        pack_hl(o[nd][0] * inv0, o[nd][1] * inv0, hi, lo);
        *(uint32_t*)&g_Xhi[row0 * 1024 + col] = hi;
        *(uint32_t*)&g_Xlo[row0 * 1024 + col] = lo;
        pack_hl(o[nd][2] * inv1, o[nd][3] * inv1, hi, lo);
        *(uint32_t*)&g_Xhi[row1 * 1024 + col] = hi;
        *(uint32_t*)&g_Xlo[row1 * 1024 + col] = lo;
    }
}

// ---------------------------------------------------------------------------
extern "C" void kernel_launch(void* const* d_in, const int* in_sizes, int n_in,
                              void* d_out, int out_size)
{
    const float* q  = (const float*)d_in[0];
    const float* w3 = (const float*)d_in[1];
    const float* b3 = (const float*)d_in[2];
    const float* ow = (const float*)d_in[3];
    const float* ob = (const float*)d_in[4];
    const float* pe = (const float*)d_in[5];
    float* out = (float*)d_out;

    cudaFuncSetAttribute(attn_mma, cudaFuncAttributeMaxDynamicSharedMemorySize,
                         ATTN_SMEM);
    cudaFuncSetAttribute(mma_gemm<0>, cudaFuncAttributeMaxDynamicSharedMemorySize,
                         GEMM_SMEM);
    cudaFuncSetAttribute(mma_gemm<1>, cudaFuncAttributeMaxDynamicSharedMemorySize,
                         GEMM_SMEM);

    split_all<<<8192, 256>>>(q, w3, ow);                         // launch 0
    mma_gemm<0><<<dim3(24, 16), 512, GEMM_SMEM>>>(b3, nullptr);  // launch 1
    bias_gemm<<<1024, 256>>>(pe);                                // launch 2
    attn_mma<<<dim3(8, 64), 256, ATTN_SMEM>>>();                 // launch 3 (ncu)
    mma_gemm<1><<<dim3(8, 16), 512, GEMM_SMEM>>>(ob, out);       // launch 4
}

// round 16
// speedup vs baseline: 1.1954x; 1.1954x over previous
#include <cuda_runtime.h>
#include <cuda_fp16.h>
#include <cstdint>

// ---------------------------------------------------------------------------
// RelativeSelfAttention: B=4, L=1024, E=1024, H=16, D=64, K=64 (129 PE rows)
// R16: fp16 split replaces bf16. Projection GEMMs 2-term (Ah*Bh + Ah*Bl,
//      activation-lo dropped); attention stays 3-term. ~1/3 fewer GEMM MMAs.
// ---------------------------------------------------------------------------

#define NBH   64
#define BSTR  132

__device__ float g_bias[NBH * 1024 * BSTR];

__device__ __half g_Ahi[4096 * 1024];
__device__ __half g_Whi[3072 * 1024], g_Wlo[3072 * 1024];
__device__ __half g_OWhi[1024 * 1024], g_OWlo[1024 * 1024];
__device__ __half g_Xhi[4096 * 1024];
__device__ __half g_Qhi[NBH * 65536], g_Qlo[NBH * 65536];
__device__ __half g_Khi[NBH * 65536], g_Klo[NBH * 65536];
__device__ __half g_Vhi[NBH * 65536], g_Vlo[NBH * 65536];

// ------------------------------- PTX helpers -------------------------------
__device__ __forceinline__ uint32_t s2u(const void* p) {
    return (uint32_t)__cvta_generic_to_shared(p);
}
__device__ __forceinline__ void ldsm_x4(uint32_t* r, uint32_t addr) {
    asm volatile("ldmatrix.sync.aligned.m8n8.x4.shared.b16 {%0,%1,%2,%3}, [%4];"
        : "=r"(r[0]), "=r"(r[1]), "=r"(r[2]), "=r"(r[3]) : "r"(addr));
}
__device__ __forceinline__ void ldsm_x4_t(uint32_t* r, uint32_t addr) {
    asm volatile("ldmatrix.sync.aligned.m8n8.x4.trans.shared.b16 {%0,%1,%2,%3}, [%4];"
        : "=r"(r[0]), "=r"(r[1]), "=r"(r[2]), "=r"(r[3]) : "r"(addr));
}
__device__ __forceinline__ void mma16816(float* c, const uint32_t* a,
                                         const uint32_t* b) {
    asm volatile(
        "mma.sync.aligned.m16n8k16.row.col.f32.f16.f16.f32 "
        "{%0,%1,%2,%3}, {%4,%5,%6,%7}, {%8,%9}, {%0,%1,%2,%3};"
        : "+f"(c[0]), "+f"(c[1]), "+f"(c[2]), "+f"(c[3])
        : "r"(a[0]), "r"(a[1]), "r"(a[2]), "r"(a[3]), "r"(b[0]), "r"(b[1]));
}
__device__ __forceinline__ void cpa16(uint32_t dst, const void* src) {
    asm volatile("cp.async.cg.shared.global [%0], [%1], 16;"
                 :: "r"(dst), "l"(src) : "memory");
}
__device__ __forceinline__ void cpa_commit() {
    asm volatile("cp.async.commit_group;" ::: "memory");
}
template <int N>
__device__ __forceinline__ void cpa_wait() {
    asm volatile("cp.async.wait_group %0;" :: "n"(N) : "memory");
}
__device__ __forceinline__ void pack_hl(float v0, float v1,
                                        uint32_t& hi, uint32_t& lo) {
    __half h0 = __float2half_rn(v0), h1 = __float2half_rn(v1);
    float l0 = v0 - __half2float(h0), l1 = v1 - __half2float(h1);
    __half2 H = __halves2half2(h0, h1);
    __half2 L = __halves2half2(__float2half_rn(l0), __float2half_rn(l1));
    hi = *(uint32_t*)&H; lo = *(uint32_t*)&L;
}
__device__ __forceinline__ uint32_t pack_h(float v0, float v1) {
    __half2 H = __floats2half2_rn(v0, v1);
    return *(uint32_t*)&H;
}
__device__ __forceinline__ void split2(__half* hp, __half* lp,
                                       size_t idx, float v0, float v1) {
    uint32_t hi, lo;
    pack_hl(v0, v1, hi, lo);
    *(uint32_t*)&hp[idx] = hi;
    *(uint32_t*)&lp[idx] = lo;
}

// ---------------------------------------------------------------------------
// Merged fp32 -> fp16 split: q -> hi only; w3, out_w -> hi+lo.
// float4 ranges: q [0,1048576), w3 [1048576,1835008), ow [1835008,2097152)
// ---------------------------------------------------------------------------
__global__ __launch_bounds__(256) void split_all(
    const float* __restrict__ q, const float* __restrict__ w3,
    const float* __restrict__ ow)
{
    int i = blockIdx.x * 256 + threadIdx.x;
    if (i < 1048576) {
        float4 v = ((const float4*)q)[i];
        __half h[4] = {__float2half_rn(v.x), __float2half_rn(v.y),
                       __float2half_rn(v.z), __float2half_rn(v.w)};
        *(uint2*)&g_Ahi[(size_t)i * 4] = *(uint2*)h;
        return;
    }
    const float* src;
    __half *hp, *lp;
    int off;
    if (i < 1835008) { src = w3; hp = g_Whi;  lp = g_Wlo;  off = i - 1048576; }
    else             { src = ow; hp = g_OWhi; lp = g_OWlo; off = i - 1835008; }
    float4 v = ((const float4*)src)[off];
    __half h[4], l[4];
    float f[4] = {v.x, v.y, v.z, v.w};
    #pragma unroll
    for (int k = 0; k < 4; ++k) {
        h[k] = __float2half_rn(f[k]);
        l[k] = __float2half_rn(f[k] - __half2float(h[k]));
    }
    *(uint2*)&hp[(size_t)off * 4] = *(uint2*)h;
    *(uint2*)&lp[(size_t)off * 4] = *(uint2*)l;
}

// ---------------------------------------------------------------------------
// 2-term fp16 mma.sync GEMM: D = Ah*(Bh+Bl), cp.async double-buffered,
// 2 CTAs/SM. Stage: 3 arrays x 128 x 80B = 30720 B; 2 stages = 60 KB.
// MODE 0: A=q-hi, B=W3-split -> Q/K/V fp16 hi/lo
// MODE 1: A=X-hi, B=out_w-split -> outp
// ---------------------------------------------------------------------------
#define SPAD 40
#define ARR_B 10240
#define STG_B (3 * ARR_B)
#define GEMM_SMEM (2 * STG_B)

template <int MODE>
__global__ __launch_bounds__(256, 2) void mma_gemm(
    const float* __restrict__ bias, float* __restrict__ outp)
{
    extern __shared__ __align__(16) char gsm[];
    const uint32_t u0 = s2u(gsm);

    const __half* Ah = (MODE == 0) ? g_Ahi : g_Xhi;
    const __half* Bh = (MODE == 0) ? g_Whi : g_OWhi;
    const __half* Bl = (MODE == 0) ? g_Wlo : g_OWlo;

    const int m0 = blockIdx.y << 7;
    const int n0 = blockIdx.x << 7;
    const int tid = threadIdx.x;
    const int wid = tid >> 5, lane = tid & 31;
    const int wm = wid >> 2, wn = wid & 3;
    const int grp = lane >> 2, tig = lane & 3;

    const int lrow0 = tid >> 2,        lc40 = tid & 3;
    const int lrow1 = (tid + 256) >> 2, lc41 = (tid + 256) & 3;
    const uint32_t sb0 = (uint32_t)(lrow0 * SPAD + lc40 * 8) * 2;
    const uint32_t sb1 = (uint32_t)(lrow1 * SPAD + lc41 * 8) * 2;

    const uint32_t aBase = (uint32_t)(((wm * 64) + (lane & 15)) * SPAD +
                                      (lane >> 4) * 8) * 2;
    const uint32_t bBase = (uint32_t)(((wn * 32) + (lane & 7)) * SPAD +
                                      ((lane >> 3) & 1) * 8) * 2;

    float acc[4][4][4] = {};

    auto issue = [&](int stage, int kc) {
        const int ko = kc * 4;
        const size_t ga0 = (size_t)(m0 + lrow0) * 128 + ko + lc40;
        const size_t ga1 = (size_t)(m0 + lrow1) * 128 + ko + lc41;
        const size_t gb0 = (size_t)(n0 + lrow0) * 128 + ko + lc40;
        const size_t gb1 = (size_t)(n0 + lrow1) * 128 + ko + lc41;
        const uint32_t s = u0 + (uint32_t)stage * STG_B;
        cpa16(s + sb0,             (const uint4*)Ah + ga0);
        cpa16(s + sb1,             (const uint4*)Ah + ga1);
        cpa16(s + ARR_B + sb0,     (const uint4*)Bh + gb0);
        cpa16(s + ARR_B + sb1,     (const uint4*)Bh + gb1);
        cpa16(s + 2 * ARR_B + sb0, (const uint4*)Bl + gb0);
        cpa16(s + 2 * ARR_B + sb1, (const uint4*)Bl + gb1);
        cpa_commit();
    };

    issue(0, 0);
    issue(1, 1);

    for (int kc = 0; kc < 32; ++kc) {
        cpa_wait<1>();
        __syncthreads();

        const uint32_t uAh = u0 + (uint32_t)(kc & 1) * STG_B;
        const uint32_t uBh = uAh + ARR_B;
        const uint32_t uBl = uBh + ARR_B;

        #pragma unroll
        for (int ks = 0; ks < 2; ++ks) {
            const uint32_t kb = (uint32_t)(ks * 16) * 2;
            uint32_t fbh[4][2], fbl[4][2];
            #pragma unroll
            for (int ni = 0; ni < 4; ++ni) {
                uint32_t off = bBase + kb + (uint32_t)(ni * 8 * SPAD) * 2;
                asm volatile("ldmatrix.sync.aligned.m8n8.x2.shared.b16 {%0,%1}, [%2];"
                    : "=r"(fbh[ni][0]), "=r"(fbh[ni][1]) : "r"(uBh + off));
                asm volatile("ldmatrix.sync.aligned.m8n8.x2.shared.b16 {%0,%1}, [%2];"
                    : "=r"(fbl[ni][0]), "=r"(fbl[ni][1]) : "r"(uBl + off));
            }
            #pragma unroll
            for (int mi = 0; mi < 4; ++mi) {
                uint32_t fah[4];
                uint32_t off = aBase + kb + (uint32_t)(mi * 16 * SPAD) * 2;
                ldsm_x4(fah, uAh + off);
                #pragma unroll
                for (int ni = 0; ni < 4; ++ni) {
                    mma16816(acc[mi][ni], fah, fbh[ni]);
                    mma16816(acc[mi][ni], fah, fbl[ni]);
                }
            }
        }
        __syncthreads();
        if (kc + 2 < 32) issue(kc & 1, kc + 2);
    }

    #pragma unroll
    for (int mi = 0; mi < 4; ++mi) {
        #pragma unroll
        for (int ni = 0; ni < 4; ++ni) {
            const int col = n0 + wn * 32 + ni * 8 + tig * 2;
            const float bv0 = bias[col], bv1 = bias[col + 1];
            #pragma unroll
            for (int rh = 0; rh < 2; ++rh) {
                const int row = m0 + wm * 64 + mi * 16 + grp + rh * 8;
                float v0 = acc[mi][ni][rh * 2 + 0] + bv0;
                float v1 = acc[mi][ni][rh * 2 + 1] + bv1;
                if (MODE == 0) {
                    const int part = col >> 10;
                    const int h = (col & 1023) >> 6;
                    const int d = col & 63;
                    const int b = row >> 10, l = row & 1023;
                    size_t idx = ((size_t)((b << 4) + h) * 1024 + l) * 64 + d;
                    if (part == 0) {
                        split2(g_Qhi, g_Qlo, idx, v0 * 0.125f, v1 * 0.125f);
                    } else if (part == 1) {
                        split2(g_Khi, g_Klo, idx, v0, v1);
                    } else {
                        split2(g_Vhi, g_Vlo, idx, v0, v1);
                    }
                } else {
                    float2 o = {v0, v1};
                    *(float2*)&outp[row * 1024 + col] = o;
                }
            }
        }
    }
}

// ---------------------------------------------------------------------------
// Stage 2: bias_r[row, r] = q_scaled[row,:] . rel_pe[r,:]
// q reconstructed from fp16 hi+lo (error ~2^-22). Conflict-free pes_t.
// ---------------------------------------------------------------------------
__global__ __launch_bounds__(256) void bias_gemm(const float* __restrict__ pe)
{
    __shared__ float pes_t[64 * 132];
    __shared__ float qs[64 * 64];
    const int tid = threadIdx.x;
    const int row0 = blockIdx.x << 6;
    for (int i = tid; i < 129 * 64; i += 256) {
        int r = i >> 6, d = i & 63;
        pes_t[d * 132 + r] = pe[i];
    }
    for (int i = tid; i < 64 * 64; i += 256) {
        size_t g = (size_t)row0 * 64 + i;
        qs[i] = __half2float(g_Qhi[g]) + __half2float(g_Qlo[g]);
    }
    __syncthreads();
    for (int idx = tid; idx < 64 * 129; idx += 256) {
        int r = idx / 129, c = idx - r * 129;
        const float* qrow = &qs[r << 6];
        float s = 0.f;
        #pragma unroll
        for (int d = 0; d < 64; ++d)
            s = fmaf(qrow[d], pes_t[d * 132 + c], s);
        g_bias[(size_t)(row0 + r) * BSTR + c] = s;
    }
}

// ---------------------------------------------------------------------------
// Stage 3: flash attention, fp16 3-term (S and PV). X written hi-only.
// ---------------------------------------------------------------------------
#define AT_SPAD 72
#define AT_ARR_B (64 * AT_SPAD * 2)
#define AT_STG_B (4 * AT_ARR_B)
#define AT_Q_B   (128 * AT_SPAD * 2)
#define ATTN_SMEM (2 * AT_STG_B + 2 * AT_Q_B)
#define NJT 16

__global__ __launch_bounds__(256, 2) void attn_mma()
{
    extern __shared__ __align__(16) char smem_raw[];
    const uint32_t u0 = s2u(smem_raw);
    const uint32_t uQh = u0 + 2 * AT_STG_B;
    const uint32_t uQl = uQh + AT_Q_B;

    const int bh = blockIdx.y;
    const int i0 = blockIdx.x << 7;
    const int tid = threadIdx.x;
    const int w = tid >> 5, lane = tid & 31;
    const int grp = lane >> 2, tig = lane & 3;

    const uint4* gKh = (const uint4*)(g_Khi + (size_t)bh * 65536);
    const uint4* gKl = (const uint4*)(g_Klo + (size_t)bh * 65536);
    const uint4* gVh = (const uint4*)(g_Vhi + (size_t)bh * 65536);
    const uint4* gVl = (const uint4*)(g_Vlo + (size_t)bh * 65536);

    const int cr = tid >> 2;
    const int cc = (tid & 3) * 2;
    const uint32_t cdst = (uint32_t)(cr * AT_SPAD * 2) + (uint32_t)cc * 16;
    auto issue_kv = [&](int jt) {
        const uint32_t s = u0 + (uint32_t)(jt & 1) * AT_STG_B;
        const uint4* kh = gKh + jt * 512 + cr * 8 + cc;
        const uint4* kl = gKl + jt * 512 + cr * 8 + cc;
        const uint4* vh = gVh + jt * 512 + cr * 8 + cc;
        const uint4* vl = gVl + jt * 512 + cr * 8 + cc;
        cpa16(s + cdst, kh);                    cpa16(s + cdst + 16, kh + 1);
        cpa16(s + AT_ARR_B + cdst, kl);         cpa16(s + AT_ARR_B + cdst + 16, kl + 1);
        cpa16(s + 2 * AT_ARR_B + cdst, vh);     cpa16(s + 2 * AT_ARR_B + cdst + 16, vh + 1);
        cpa16(s + 3 * AT_ARR_B + cdst, vl);     cpa16(s + 3 * AT_ARR_B + cdst + 16, vl + 1);
        cpa_commit();
    };

    issue_kv(0);

    {
        const size_t qbase = (size_t)bh * 65536 + (size_t)i0 * 64;
        const uint4* srcH = (const uint4*)(g_Qhi + qbase);
        const uint4* srcL = (const uint4*)(g_Qlo + qbase);
        __half* tQh = (__half*)(smem_raw + 2 * AT_STG_B);
        __half* tQl = tQh + 128 * AT_SPAD;
        #pragma unroll
        for (int k = 0; k < 4; ++k) {
            int u = tid + k * 256;
            int r = u >> 3, c = (u & 7) * 8;
            *(uint4*)&tQh[r * AT_SPAD + c] = srcH[u];
            *(uint4*)&tQl[r * AT_SPAD + c] = srcL[u];
        }
    }

    const int r0g = i0 + w * 16 + grp;
    const int r1g = r0g + 8;
    const float* browG0 = g_bias + (size_t)(bh * 1024 + r0g) * BSTR + 64;
    const float* browG1 = g_bias + (size_t)(bh * 1024 + r1g) * BSTR + 64;
    const float clo0 = __ldg(browG0 - 64), chi0 = __ldg(browG0 + 64);
    const float clo1 = __ldg(browG1 - 64), chi1 = __ldg(browG1 + 64);

    float mr[2] = {-1e30f, -1e30f};
    float lr[2] = {0.f, 0.f};
    float o[8][4] = {};

    const uint32_t qro = (uint32_t)((w * 16 + (lane & 15)) * AT_SPAD +
                                    (lane >> 4) * 8) * 2;

    for (int jt = 0; jt < NJT; ++jt) {
        if (jt + 1 < NJT) issue_kv(jt + 1);
        if (jt + 1 < NJT) cpa_wait<1>(); else cpa_wait<0>();
        __syncthreads();

        const uint32_t uKh = u0 + (uint32_t)(jt & 1) * AT_STG_B;
        const uint32_t uKl = uKh + AT_ARR_B;
        const uint32_t uVh = uKl + AT_ARR_B;
        const uint32_t uVl = uVh + AT_ARR_B;
        const int j0 = jt << 6;

        float s[8][4];
        #pragma unroll
        for (int jb = 0; jb < 8; ++jb)
            #pragma unroll
            for (int e = 0; e < 4; ++e) s[jb][e] = 0.f;

        #pragma unroll
        for (int ks = 0; ks < 4; ++ks) {
            uint32_t qh[4], ql[4];
            ldsm_x4(qh, uQh + qro + ks * 32);
            ldsm_x4(ql, uQl + qro + ks * 32);
            #pragma unroll
            for (int jp = 0; jp < 4; ++jp) {
                uint32_t kfh[4], kfl[4];
                uint32_t off = (uint32_t)((jp * 16 + (lane & 7) +
                                           ((lane >> 4) << 3)) * AT_SPAD +
                                          ks * 16 + ((lane >> 3) & 1) * 8) * 2;
                ldsm_x4(kfh, uKh + off);
                ldsm_x4(kfl, uKl + off);
                mma16816(s[2 * jp],     qh, kfh);
                mma16816(s[2 * jp],     qh, kfl);
                mma16816(s[2 * jp],     ql, kfh);
                mma16816(s[2 * jp + 1], qh, kfh + 2);
                mma16816(s[2 * jp + 1], qh, kfl + 2);
                mma16816(s[2 * jp + 1], ql, kfh + 2);
            }
        }

        if (j0 + 63 - r0g <= -64) {
            #pragma unroll
            for (int jb = 0; jb < 8; ++jb) { s[jb][0] += clo0; s[jb][1] += clo0; }
        } else if (j0 - r0g >= 64) {
            #pragma unroll
            for (int jb = 0; jb < 8; ++jb) { s[jb][0] += chi0; s[jb][1] += chi0; }
        } else {
            const int dbase0 = j0 + tig * 2 - r0g;
            #pragma unroll
            for (int jb = 0; jb < 8; ++jb) {
                int dA = min(max(dbase0 + jb * 8,     -64), 64);
                int dB = min(max(dbase0 + jb * 8 + 1, -64), 64);
                s[jb][0] += __ldg(browG0 + dA);
                s[jb][1] += __ldg(browG0 + dB);
            }
        }
        if (j0 + 63 - r1g <= -64) {
            #pragma unroll
            for (int jb = 0; jb < 8; ++jb) { s[jb][2] += clo1; s[jb][3] += clo1; }
        } else if (j0 - r1g >= 64) {
            #pragma unroll
            for (int jb = 0; jb < 8; ++jb) { s[jb][2] += chi1; s[jb][3] += chi1; }
        } else {
            const int dbase1 = j0 + tig * 2 - r1g;
            #pragma unroll
            for (int jb = 0; jb < 8; ++jb) {
                int dC = min(max(dbase1 + jb * 8,     -64), 64);
                int dD = min(max(dbase1 + jb * 8 + 1, -64), 64);
                s[jb][2] += __ldg(browG1 + dC);
                s[jb][3] += __ldg(browG1 + dD);
            }
        }

        float mx0 = -1e30f, mx1 = -1e30f;
        #pragma unroll
        for (int jb = 0; jb < 8; ++jb) {
            mx0 = fmaxf(mx0, fmaxf(s[jb][0], s[jb][1]));
            mx1 = fmaxf(mx1, fmaxf(s[jb][2], s[jb][3]));
        }
        mx0 = fmaxf(mx0, __shfl_xor_sync(0xffffffffu, mx0, 1));
        mx0 = fmaxf(mx0, __shfl_xor_sync(0xffffffffu, mx0, 2));
        mx1 = fmaxf(mx1, __shfl_xor_sync(0xffffffffu, mx1, 1));
        mx1 = fmaxf(mx1, __shfl_xor_sync(0xffffffffu, mx1, 2));
        float nm0 = fmaxf(mr[0], mx0), nm1 = fmaxf(mr[1], mx1);
        float sc0 = __expf(mr[0] - nm0), sc1 = __expf(mr[1] - nm1);
        float ps0 = 0.f, ps1 = 0.f;
        #pragma unroll
        for (int jb = 0; jb < 8; ++jb) {
            s[jb][0] = __expf(s[jb][0] - nm0);
            s[jb][1] = __expf(s[jb][1] - nm0);
            s[jb][2] = __expf(s[jb][2] - nm1);
            s[jb][3] = __expf(s[jb][3] - nm1);
            ps0 += s[jb][0] + s[jb][1];
            ps1 += s[jb][2] + s[jb][3];
        }
        ps0 += __shfl_xor_sync(0xffffffffu, ps0, 1);
        ps0 += __shfl_xor_sync(0xffffffffu, ps0, 2);
        ps1 += __shfl_xor_sync(0xffffffffu, ps1, 1);
        ps1 += __shfl_xor_sync(0xffffffffu, ps1, 2);
        lr[0] = lr[0] * sc0 + ps0; mr[0] = nm0;
        lr[1] = lr[1] * sc1 + ps1; mr[1] = nm1;
        #pragma unroll
        for (int nd = 0; nd < 8; ++nd) {
            o[nd][0] *= sc0; o[nd][1] *= sc0;
            o[nd][2] *= sc1; o[nd][3] *= sc1;
        }

        #pragma unroll
        for (int kk = 0; kk < 4; ++kk) {
            uint32_t ah[4], al[4];
            pack_hl(s[2 * kk][0],     s[2 * kk][1],     ah[0], al[0]);
            pack_hl(s[2 * kk][2],     s[2 * kk][3],     ah[1], al[1]);
            pack_hl(s[2 * kk + 1][0], s[2 * kk + 1][1], ah[2], al[2]);
            pack_hl(s[2 * kk + 1][2], s[2 * kk + 1][3], ah[3], al[3]);
            #pragma unroll
            for (int np = 0; np < 4; ++np) {
                uint32_t vfh[4], vfl[4];
                uint32_t off = (uint32_t)((kk * 16 + (lane & 7) +
                                           ((lane >> 3) & 1) * 8) * AT_SPAD +
                                          np * 16 + (lane >> 4) * 8) * 2;
                ldsm_x4_t(vfh, uVh + off);
                ldsm_x4_t(vfl, uVl + off);
                mma16816(o[2 * np],     ah, vfh);
                mma16816(o[2 * np],     ah, vfl);
                mma16816(o[2 * np],     al, vfh);
                mma16816(o[2 * np + 1], ah, vfh + 2);
                mma16816(o[2 * np + 1], ah, vfl + 2);
                mma16816(o[2 * np + 1], al, vfh + 2);
            }
        }
        __syncthreads();
    }

    // finalize + write X hi (fp16) in (b,l,e) layout; lo not needed (2-term GEMM)
    const float inv0 = 1.0f / lr[0], inv1 = 1.0f / lr[1];
    const int b = bh >> 4, h = bh & 15;
    const size_t row0 = (size_t)(b * 1024 + i0 + w * 16 + grp);
    const size_t row1 = row0 + 8;
    #pragma unroll
    for (int nd = 0; nd < 8; ++nd) {
        const int col = h * 64 + nd * 8 + tig * 2;
        *(uint32_t*)&g_Xhi[row0 * 1024 + col] =
            pack_h(o[nd][0] * inv0, o[nd][1] * inv0);
        *(uint32_t*)&g_Xhi[row1 * 1024 + col] =
            pack_h(o[nd][2] * inv1, o[nd][3] * inv1);
    }
}

// ---------------------------------------------------------------------------
extern "C" void kernel_launch(void* const* d_in, const int* in_sizes, int n_in,
                              void* d_out, int out_size)
{
    const float* q  = (const float*)d_in[0];
    const float* w3 = (const float*)d_in[1];
    const float* b3 = (const float*)d_in[2];
    const float* ow = (const float*)d_in[3];
    const float* ob = (const float*)d_in[4];
    const float* pe = (const float*)d_in[5];
    float* out = (float*)d_out;

    cudaFuncSetAttribute(attn_mma, cudaFuncAttributeMaxDynamicSharedMemorySize,
                         ATTN_SMEM);
    cudaFuncSetAttribute(mma_gemm<0>, cudaFuncAttributeMaxDynamicSharedMemorySize,
                         GEMM_SMEM);
    cudaFuncSetAttribute(mma_gemm<1>, cudaFuncAttributeMaxDynamicSharedMemorySize,
                         GEMM_SMEM);

    split_all<<<8192, 256>>>(q, w3, ow);                         // launch 0
    mma_gemm<0><<<dim3(24, 32), 256, GEMM_SMEM>>>(b3, nullptr);  // launch 1
    bias_gemm<<<1024, 256>>>(pe);                                // launch 2
    attn_mma<<<dim3(8, 64), 256, ATTN_SMEM>>>();                 // launch 3 (ncu)
    mma_gemm<1><<<dim3(8, 32), 256, GEMM_SMEM>>>(ob, out);       // launch 4
}

// round 17
// speedup vs baseline: 1.2617x; 1.0554x over previous
#include <cuda_runtime.h>
#include <cuda_fp16.h>
#include <cstdint>

// ---------------------------------------------------------------------------
// RelativeSelfAttention: B=4, L=1024, E=1024, H=16, D=64, K=64 (129 PE rows)
// R17: attention PV 2-term (Ph*Vh + Ph*Vl); S stays 3-term.
//      Projection GEMMs 2-term fp16 (R16).
// ---------------------------------------------------------------------------

#define NBH   64
#define BSTR  132

__device__ float g_bias[NBH * 1024 * BSTR];

__device__ __half g_Ahi[4096 * 1024];
__device__ __half g_Whi[3072 * 1024], g_Wlo[3072 * 1024];
__device__ __half g_OWhi[1024 * 1024], g_OWlo[1024 * 1024];
__device__ __half g_Xhi[4096 * 1024];
__device__ __half g_Qhi[NBH * 65536], g_Qlo[NBH * 65536];
__device__ __half g_Khi[NBH * 65536], g_Klo[NBH * 65536];
__device__ __half g_Vhi[NBH * 65536], g_Vlo[NBH * 65536];

// ------------------------------- PTX helpers -------------------------------
__device__ __forceinline__ uint32_t s2u(const void* p) {
    return (uint32_t)__cvta_generic_to_shared(p);
}
__device__ __forceinline__ void ldsm_x4(uint32_t* r, uint32_t addr) {
    asm volatile("ldmatrix.sync.aligned.m8n8.x4.shared.b16 {%0,%1,%2,%3}, [%4];"
        : "=r"(r[0]), "=r"(r[1]), "=r"(r[2]), "=r"(r[3]) : "r"(addr));
}
__device__ __forceinline__ void ldsm_x4_t(uint32_t* r, uint32_t addr) {
    asm volatile("ldmatrix.sync.aligned.m8n8.x4.trans.shared.b16 {%0,%1,%2,%3}, [%4];"
        : "=r"(r[0]), "=r"(r[1]), "=r"(r[2]), "=r"(r[3]) : "r"(addr));
}
__device__ __forceinline__ void mma16816(float* c, const uint32_t* a,
                                         const uint32_t* b) {
    asm volatile(
        "mma.sync.aligned.m16n8k16.row.col.f32.f16.f16.f32 "
        "{%0,%1,%2,%3}, {%4,%5,%6,%7}, {%8,%9}, {%0,%1,%2,%3};"
        : "+f"(c[0]), "+f"(c[1]), "+f"(c[2]), "+f"(c[3])
        : "r"(a[0]), "r"(a[1]), "r"(a[2]), "r"(a[3]), "r"(b[0]), "r"(b[1]));
}
__device__ __forceinline__ void cpa16(uint32_t dst, const void* src) {
    asm volatile("cp.async.cg.shared.global [%0], [%1], 16;"
                 :: "r"(dst), "l"(src) : "memory");
}
__device__ __forceinline__ void cpa_commit() {
    asm volatile("cp.async.commit_group;" ::: "memory");
}
template <int N>
__device__ __forceinline__ void cpa_wait() {
    asm volatile("cp.async.wait_group %0;" :: "n"(N) : "memory");
}
__device__ __forceinline__ void pack_hl(float v0, float v1,
                                        uint32_t& hi, uint32_t& lo) {
    __half h0 = __float2half_rn(v0), h1 = __float2half_rn(v1);
    float l0 = v0 - __half2float(h0), l1 = v1 - __half2float(h1);
    __half2 H = __halves2half2(h0, h1);
    __half2 L = __halves2half2(__float2half_rn(l0), __float2half_rn(l1));
    hi = *(uint32_t*)&H; lo = *(uint32_t*)&L;
}
__device__ __forceinline__ uint32_t pack_h(float v0, float v1) {
    __half2 H = __floats2half2_rn(v0, v1);
    return *(uint32_t*)&H;
}
__device__ __forceinline__ void split2(__half* hp, __half* lp,
                                       size_t idx, float v0, float v1) {
    uint32_t hi, lo;
    pack_hl(v0, v1, hi, lo);
    *(uint32_t*)&hp[idx] = hi;
    *(uint32_t*)&lp[idx] = lo;
}

// ---------------------------------------------------------------------------
// Merged fp32 -> fp16 split: q -> hi only; w3, out_w -> hi+lo.
// ---------------------------------------------------------------------------
__global__ __launch_bounds__(256) void split_all(
    const float* __restrict__ q, const float* __restrict__ w3,
    const float* __restrict__ ow)
{
    int i = blockIdx.x * 256 + threadIdx.x;
    if (i < 1048576) {
        float4 v = ((const float4*)q)[i];
        __half h[4] = {__float2half_rn(v.x), __float2half_rn(v.y),
                       __float2half_rn(v.z), __float2half_rn(v.w)};
        *(uint2*)&g_Ahi[(size_t)i * 4] = *(uint2*)h;
        return;
    }
    const float* src;
    __half *hp, *lp;
    int off;
    if (i < 1835008) { src = w3; hp = g_Whi;  lp = g_Wlo;  off = i - 1048576; }
    else             { src = ow; hp = g_OWhi; lp = g_OWlo; off = i - 1835008; }
    float4 v = ((const float4*)src)[off];
    __half h[4], l[4];
    float f[4] = {v.x, v.y, v.z, v.w};
    #pragma unroll
    for (int k = 0; k < 4; ++k) {
        h[k] = __float2half_rn(f[k]);
        l[k] = __float2half_rn(f[k] - __half2float(h[k]));
    }
    *(uint2*)&hp[(size_t)off * 4] = *(uint2*)h;
    *(uint2*)&lp[(size_t)off * 4] = *(uint2*)l;
}

// ---------------------------------------------------------------------------
// 2-term fp16 mma.sync GEMM: D = Ah*(Bh+Bl), cp.async double-buffered,
// 2 CTAs/SM. (unchanged from R16)
// ---------------------------------------------------------------------------
#define SPAD 40
#define ARR_B 10240
#define STG_B (3 * ARR_B)
#define GEMM_SMEM (2 * STG_B)

template <int MODE>
__global__ __launch_bounds__(256, 2) void mma_gemm(
    const float* __restrict__ bias, float* __restrict__ outp)
{
    extern __shared__ __align__(16) char gsm[];
    const uint32_t u0 = s2u(gsm);

    const __half* Ah = (MODE == 0) ? g_Ahi : g_Xhi;
    const __half* Bh = (MODE == 0) ? g_Whi : g_OWhi;
    const __half* Bl = (MODE == 0) ? g_Wlo : g_OWlo;

    const int m0 = blockIdx.y << 7;
    const int n0 = blockIdx.x << 7;
    const int tid = threadIdx.x;
    const int wid = tid >> 5, lane = tid & 31;
    const int wm = wid >> 2, wn = wid & 3;
    const int grp = lane >> 2, tig = lane & 3;

    const int lrow0 = tid >> 2,        lc40 = tid & 3;
    const int lrow1 = (tid + 256) >> 2, lc41 = (tid + 256) & 3;
    const uint32_t sb0 = (uint32_t)(lrow0 * SPAD + lc40 * 8) * 2;
    const uint32_t sb1 = (uint32_t)(lrow1 * SPAD + lc41 * 8) * 2;

    const uint32_t aBase = (uint32_t)(((wm * 64) + (lane & 15)) * SPAD +
                                      (lane >> 4) * 8) * 2;
    const uint32_t bBase = (uint32_t)(((wn * 32) + (lane & 7)) * SPAD +
                                      ((lane >> 3) & 1) * 8) * 2;

    float acc[4][4][4] = {};

    auto issue = [&](int stage, int kc) {
        const int ko = kc * 4;
        const size_t ga0 = (size_t)(m0 + lrow0) * 128 + ko + lc40;
        const size_t ga1 = (size_t)(m0 + lrow1) * 128 + ko + lc41;
        const size_t gb0 = (size_t)(n0 + lrow0) * 128 + ko + lc40;
        const size_t gb1 = (size_t)(n0 + lrow1) * 128 + ko + lc41;
        const uint32_t s = u0 + (uint32_t)stage * STG_B;
        cpa16(s + sb0,             (const uint4*)Ah + ga0);
        cpa16(s + sb1,             (const uint4*)Ah + ga1);
        cpa16(s + ARR_B + sb0,     (const uint4*)Bh + gb0);
        cpa16(s + ARR_B + sb1,     (const uint4*)Bh + gb1);
        cpa16(s + 2 * ARR_B + sb0, (const uint4*)Bl + gb0);
        cpa16(s + 2 * ARR_B + sb1, (const uint4*)Bl + gb1);
        cpa_commit();
    };

    issue(0, 0);
    issue(1, 1);

    for (int kc = 0; kc < 32; ++kc) {
        cpa_wait<1>();
        __syncthreads();

        const uint32_t uAh = u0 + (uint32_t)(kc & 1) * STG_B;
        const uint32_t uBh = uAh + ARR_B;
        const uint32_t uBl = uBh + ARR_B;

        #pragma unroll
        for (int ks = 0; ks < 2; ++ks) {
            const uint32_t kb = (uint32_t)(ks * 16) * 2;
            uint32_t fbh[4][2], fbl[4][2];
            #pragma unroll
            for (int ni = 0; ni < 4; ++ni) {
                uint32_t off = bBase + kb + (uint32_t)(ni * 8 * SPAD) * 2;
                asm volatile("ldmatrix.sync.aligned.m8n8.x2.shared.b16 {%0,%1}, [%2];"
                    : "=r"(fbh[ni][0]), "=r"(fbh[ni][1]) : "r"(uBh + off));
                asm volatile("ldmatrix.sync.aligned.m8n8.x2.shared.b16 {%0,%1}, [%2];"
                    : "=r"(fbl[ni][0]), "=r"(fbl[ni][1]) : "r"(uBl + off));
            }
            #pragma unroll
            for (int mi = 0; mi < 4; ++mi) {
                uint32_t fah[4];
                uint32_t off = aBase + kb + (uint32_t)(mi * 16 * SPAD) * 2;
                ldsm_x4(fah, uAh + off);
                #pragma unroll
                for (int ni = 0; ni < 4; ++ni) {
                    mma16816(acc[mi][ni], fah, fbh[ni]);
                    mma16816(acc[mi][ni], fah, fbl[ni]);
                }
            }
        }
        __syncthreads();
        if (kc + 2 < 32) issue(kc & 1, kc + 2);
    }

    #pragma unroll
    for (int mi = 0; mi < 4; ++mi) {
        #pragma unroll
        for (int ni = 0; ni < 4; ++ni) {
            const int col = n0 + wn * 32 + ni * 8 + tig * 2;
            const float bv0 = bias[col], bv1 = bias[col + 1];
            #pragma unroll
            for (int rh = 0; rh < 2; ++rh) {
                const int row = m0 + wm * 64 + mi * 16 + grp + rh * 8;
                float v0 = acc[mi][ni][rh * 2 + 0] + bv0;
                float v1 = acc[mi][ni][rh * 2 + 1] + bv1;
                if (MODE == 0) {
                    const int part = col >> 10;
                    const int h = (col & 1023) >> 6;
                    const int d = col & 63;
                    const int b = row >> 10, l = row & 1023;
                    size_t idx = ((size_t)((b << 4) + h) * 1024 + l) * 64 + d;
                    if (part == 0) {
                        split2(g_Qhi, g_Qlo, idx, v0 * 0.125f, v1 * 0.125f);
                    } else if (part == 1) {
                        split2(g_Khi, g_Klo, idx, v0, v1);
                    } else {
                        split2(g_Vhi, g_Vlo, idx, v0, v1);
                    }
                } else {
                    float2 o = {v0, v1};
                    *(float2*)&outp[row * 1024 + col] = o;
                }
            }
        }
    }
}

// ---------------------------------------------------------------------------
// Stage 2: bias_r[row, r] = q_scaled[row,:] . rel_pe[r,:]
// ---------------------------------------------------------------------------
__global__ __launch_bounds__(256) void bias_gemm(const float* __restrict__ pe)
{
    __shared__ float pes_t[64 * 132];
    __shared__ float qs[64 * 64];
    const int tid = threadIdx.x;
    const int row0 = blockIdx.x << 6;
    for (int i = tid; i < 129 * 64; i += 256) {
        int r = i >> 6, d = i & 63;
        pes_t[d * 132 + r] = pe[i];
    }
    for (int i = tid; i < 64 * 64; i += 256) {
        size_t g = (size_t)row0 * 64 + i;
        qs[i] = __half2float(g_Qhi[g]) + __half2float(g_Qlo[g]);
    }
    __syncthreads();
    for (int idx = tid; idx < 64 * 129; idx += 256) {
        int r = idx / 129, c = idx - r * 129;
        const float* qrow = &qs[r << 6];
        float s = 0.f;
        #pragma unroll
        for (int d = 0; d < 64; ++d)
            s = fmaf(qrow[d], pes_t[d * 132 + c], s);
        g_bias[(size_t)(row0 + r) * BSTR + c] = s;
    }
}

// ---------------------------------------------------------------------------
// Stage 3: flash attention, fp16. S 3-term; PV 2-term (Ph*Vh + Ph*Vl).
// ---------------------------------------------------------------------------
#define AT_SPAD 72
#define AT_ARR_B (64 * AT_SPAD * 2)
#define AT_STG_B (4 * AT_ARR_B)
#define AT_Q_B   (128 * AT_SPAD * 2)
#define ATTN_SMEM (2 * AT_STG_B + 2 * AT_Q_B)
#define NJT 16

__global__ __launch_bounds__(256, 2) void attn_mma()
{
    extern __shared__ __align__(16) char smem_raw[];
    const uint32_t u0 = s2u(smem_raw);
    const uint32_t uQh = u0 + 2 * AT_STG_B;
    const uint32_t uQl = uQh + AT_Q_B;

    const int bh = blockIdx.y;
    const int i0 = blockIdx.x << 7;
    const int tid = threadIdx.x;
    const int w = tid >> 5, lane = tid & 31;
    const int grp = lane >> 2, tig = lane & 3;

    const uint4* gKh = (const uint4*)(g_Khi + (size_t)bh * 65536);
    const uint4* gKl = (const uint4*)(g_Klo + (size_t)bh * 65536);
    const uint4* gVh = (const uint4*)(g_Vhi + (size_t)bh * 65536);
    const uint4* gVl = (const uint4*)(g_Vlo + (size_t)bh * 65536);

    const int cr = tid >> 2;
    const int cc = (tid & 3) * 2;
    const uint32_t cdst = (uint32_t)(cr * AT_SPAD * 2) + (uint32_t)cc * 16;
    auto issue_kv = [&](int jt) {
        const uint32_t s = u0 + (uint32_t)(jt & 1) * AT_STG_B;
        const uint4* kh = gKh + jt * 512 + cr * 8 + cc;
        const uint4* kl = gKl + jt * 512 + cr * 8 + cc;
        const uint4* vh = gVh + jt * 512 + cr * 8 + cc;
        const uint4* vl = gVl + jt * 512 + cr * 8 + cc;
        cpa16(s + cdst, kh);                    cpa16(s + cdst + 16, kh + 1);
        cpa16(s + AT_ARR_B + cdst, kl);         cpa16(s + AT_ARR_B + cdst + 16, kl + 1);
        cpa16(s + 2 * AT_ARR_B + cdst, vh);     cpa16(s + 2 * AT_ARR_B + cdst + 16, vh + 1);
        cpa16(s + 3 * AT_ARR_B + cdst, vl);     cpa16(s + 3 * AT_ARR_B + cdst + 16, vl + 1);
        cpa_commit();
    };

    issue_kv(0);

    {
        const size_t qbase = (size_t)bh * 65536 + (size_t)i0 * 64;
        const uint4* srcH = (const uint4*)(g_Qhi + qbase);
        const uint4* srcL = (const uint4*)(g_Qlo + qbase);
        __half* tQh = (__half*)(smem_raw + 2 * AT_STG_B);
        __half* tQl = tQh + 128 * AT_SPAD;
        #pragma unroll
        for (int k = 0; k < 4; ++k) {
            int u = tid + k * 256;
            int r = u >> 3, c = (u & 7) * 8;
            *(uint4*)&tQh[r * AT_SPAD + c] = srcH[u];
            *(uint4*)&tQl[r * AT_SPAD + c] = srcL[u];
        }
    }

    const int r0g = i0 + w * 16 + grp;
    const int r1g = r0g + 8;
    const float* browG0 = g_bias + (size_t)(bh * 1024 + r0g) * BSTR + 64;
    const float* browG1 = g_bias + (size_t)(bh * 1024 + r1g) * BSTR + 64;
    const float clo0 = __ldg(browG0 - 64), chi0 = __ldg(browG0 + 64);
    const float clo1 = __ldg(browG1 - 64), chi1 = __ldg(browG1 + 64);

    float mr[2] = {-1e30f, -1e30f};
    float lr[2] = {0.f, 0.f};
    float o[8][4] = {};

    const uint32_t qro = (uint32_t)((w * 16 + (lane & 15)) * AT_SPAD +
                                    (lane >> 4) * 8) * 2;

    for (int jt = 0; jt < NJT; ++jt) {
        if (jt + 1 < NJT) issue_kv(jt + 1);
        if (jt + 1 < NJT) cpa_wait<1>(); else cpa_wait<0>();
        __syncthreads();

        const uint32_t uKh = u0 + (uint32_t)(jt & 1) * AT_STG_B;
        const uint32_t uKl = uKh + AT_ARR_B;
        const uint32_t uVh = uKl + AT_ARR_B;
        const uint32_t uVl = uVh + AT_ARR_B;
        const int j0 = jt << 6;

        float s[8][4];
        #pragma unroll
        for (int jb = 0; jb < 8; ++jb)
            #pragma unroll
            for (int e = 0; e < 4; ++e) s[jb][e] = 0.f;

        #pragma unroll
        for (int ks = 0; ks < 4; ++ks) {
            uint32_t qh[4], ql[4];
            ldsm_x4(qh, uQh + qro + ks * 32);
            ldsm_x4(ql, uQl + qro + ks * 32);
            #pragma unroll
            for (int jp = 0; jp < 4; ++jp) {
                uint32_t kfh[4], kfl[4];
                uint32_t off = (uint32_t)((jp * 16 + (lane & 7) +
                                           ((lane >> 4) << 3)) * AT_SPAD +
                                          ks * 16 + ((lane >> 3) & 1) * 8) * 2;
                ldsm_x4(kfh, uKh + off);
                ldsm_x4(kfl, uKl + off);
                mma16816(s[2 * jp],     qh, kfh);
                mma16816(s[2 * jp],     qh, kfl);
                mma16816(s[2 * jp],     ql, kfh);
                mma16816(s[2 * jp + 1], qh, kfh + 2);
                mma16816(s[2 * jp + 1], qh, kfl + 2);
                mma16816(s[2 * jp + 1], ql, kfh + 2);
            }
        }

        if (j0 + 63 - r0g <= -64) {
            #pragma unroll
            for (int jb = 0; jb < 8; ++jb) { s[jb][0] += clo0; s[jb][1] += clo0; }
        } else if (j0 - r0g >= 64) {
            #pragma unroll
            for (int jb = 0; jb < 8; ++jb) { s[jb][0] += chi0; s[jb][1] += chi0; }
        } else {
            const int dbase0 = j0 + tig * 2 - r0g;
            #pragma unroll
            for (int jb = 0; jb < 8; ++jb) {
                int dA = min(max(dbase0 + jb * 8,     -64), 64);
                int dB = min(max(dbase0 + jb * 8 + 1, -64), 64);
                s[jb][0] += __ldg(browG0 + dA);
                s[jb][1] += __ldg(browG0 + dB);
            }
        }
        if (j0 + 63 - r1g <= -64) {
            #pragma unroll
            for (int jb = 0; jb < 8; ++jb) { s[jb][2] += clo1; s[jb][3] += clo1; }
        } else if (j0 - r1g >= 64) {
            #pragma unroll
            for (int jb = 0; jb < 8; ++jb) { s[jb][2] += chi1; s[jb][3] += chi1; }
        } else {
            const int dbase1 = j0 + tig * 2 - r1g;
            #pragma unroll
            for (int jb = 0; jb < 8; ++jb) {
                int dC = min(max(dbase1 + jb * 8,     -64), 64);
                int dD = min(max(dbase1 + jb * 8 + 1, -64), 64);
                s[jb][2] += __ldg(browG1 + dC);
                s[jb][3] += __ldg(browG1 + dD);
            }
        }

        float mx0 = -1e30f, mx1 = -1e30f;
        #pragma unroll
        for (int jb = 0; jb < 8; ++jb) {
            mx0 = fmaxf(mx0, fmaxf(s[jb][0], s[jb][1]));
            mx1 = fmaxf(mx1, fmaxf(s[jb][2], s[jb][3]));
        }
        mx0 = fmaxf(mx0, __shfl_xor_sync(0xffffffffu, mx0, 1));
        mx0 = fmaxf(mx0, __shfl_xor_sync(0xffffffffu, mx0, 2));
        mx1 = fmaxf(mx1, __shfl_xor_sync(0xffffffffu, mx1, 1));
        mx1 = fmaxf(mx1, __shfl_xor_sync(0xffffffffu, mx1, 2));
        float nm0 = fmaxf(mr[0], mx0), nm1 = fmaxf(mr[1], mx1);
        float sc0 = __expf(mr[0] - nm0), sc1 = __expf(mr[1] - nm1);
        float ps0 = 0.f, ps1 = 0.f;
        #pragma unroll
        for (int jb = 0; jb < 8; ++jb) {
            s[jb][0] = __expf(s[jb][0] - nm0);
            s[jb][1] = __expf(s[jb][1] - nm0);
            s[jb][2] = __expf(s[jb][2] - nm1);
            s[jb][3] = __expf(s[jb][3] - nm1);
            ps0 += s[jb][0] + s[jb][1];
            ps1 += s[jb][2] + s[jb][3];
        }
        ps0 += __shfl_xor_sync(0xffffffffu, ps0, 1);
        ps0 += __shfl_xor_sync(0xffffffffu, ps0, 2);
        ps1 += __shfl_xor_sync(0xffffffffu, ps1, 1);
        ps1 += __shfl_xor_sync(0xffffffffu, ps1, 2);
        lr[0] = lr[0] * sc0 + ps0; mr[0] = nm0;
        lr[1] = lr[1] * sc1 + ps1; mr[1] = nm1;
        #pragma unroll
        for (int nd = 0; nd < 8; ++nd) {
            o[nd][0] *= sc0; o[nd][1] *= sc0;
            o[nd][2] *= sc1; o[nd][3] *= sc1;
        }

        // ---- O += P V (2 terms: Ph*Vh + Ph*Vl) ----
        #pragma unroll
        for (int kk = 0; kk < 4; ++kk) {
            uint32_t ah[4];
            ah[0] = pack_h(s[2 * kk][0],     s[2 * kk][1]);
            ah[1] = pack_h(s[2 * kk][2],     s[2 * kk][3]);
            ah[2] = pack_h(s[2 * kk + 1][0], s[2 * kk + 1][1]);
            ah[3] = pack_h(s[2 * kk + 1][2], s[2 * kk + 1][3]);
            #pragma unroll
            for (int np = 0; np < 4; ++np) {
                uint32_t vfh[4], vfl[4];
                uint32_t off = (uint32_t)((kk * 16 + (lane & 7) +
                                           ((lane >> 3) & 1) * 8) * AT_SPAD +
                                          np * 16 + (lane >> 4) * 8) * 2;
                ldsm_x4_t(vfh, uVh + off);
                ldsm_x4_t(vfl, uVl + off);
                mma16816(o[2 * np],     ah, vfh);
                mma16816(o[2 * np],     ah, vfl);
                mma16816(o[2 * np + 1], ah, vfh + 2);
                mma16816(o[2 * np + 1], ah, vfl + 2);
            }
        }
        __syncthreads();
    }

    // finalize + write X hi (fp16) in (b,l,e) layout
    const float inv0 = 1.0f / lr[0], inv1 = 1.0f / lr[1];
    const int b = bh >> 4, h = bh & 15;
    const size_t row0 = (size_t)(b * 1024 + i0 + w * 16 + grp);
    const size_t row1 = row0 + 8;
    #pragma unroll
    for (int nd = 0; nd < 8; ++nd) {
        const int col = h * 64 + nd * 8 + tig * 2;
        *(uint32_t*)&g_Xhi[row0 * 1024 + col] =
            pack_h(o[nd][0] * inv0, o[nd][1] * inv0);
        *(uint32_t*)&g_Xhi[row1 * 1024 + col] =
            pack_h(o[nd][2] * inv1, o[nd][3] * inv1);
    }
}

// ---------------------------------------------------------------------------
extern "C" void kernel_launch(void* const* d_in, const int* in_sizes, int n_in,
                              void* d_out, int out_size)
{
    const float* q  = (const float*)d_in[0];
    const float* w3 = (const float*)d_in[1];
    const float* b3 = (const float*)d_in[2];
    const float* ow = (const float*)d_in[3];
    const float* ob = (const float*)d_in[4];
    const float* pe = (const float*)d_in[5];
    float* out = (float*)d_out;

    cudaFuncSetAttribute(attn_mma, cudaFuncAttributeMaxDynamicSharedMemorySize,
                         ATTN_SMEM);
    cudaFuncSetAttribute(mma_gemm<0>, cudaFuncAttributeMaxDynamicSharedMemorySize,
                         GEMM_SMEM);
    cudaFuncSetAttribute(mma_gemm<1>, cudaFuncAttributeMaxDynamicSharedMemorySize,
                         GEMM_SMEM);

    split_all<<<8192, 256>>>(q, w3, ow);                         // launch 0
    mma_gemm<0><<<dim3(24, 32), 256, GEMM_SMEM>>>(b3, nullptr);  // launch 1
    bias_gemm<<<1024, 256>>>(pe);                                // launch 2
    attn_mma<<<dim3(8, 64), 256, ATTN_SMEM>>>();                 // launch 3 (ncu)
    mma_gemm<1><<<dim3(8, 32), 256, GEMM_SMEM>>>(ob, out);       // launch 4
}